// round 14
// baseline (speedup 1.0000x reference)
#include <cuda_runtime.h>
#include <cuda_bf16.h>
#include <cuda_fp16.h>
#include <cstdint>
#include <cstring>

// ---------------------------------------------------------------------------
// B=128, D=2048, M=8192, C=2048, K_ITERS=1024, TAU=0.5
// ---------------------------------------------------------------------------
#define B_DIM 128
#define D_DIM 2048
#define M_DIM 8192
#define C_DIM 2048
#define K_ITERS 1024
#define F32_TINY 1.17549435e-38f

// fp16 split activation buffers (ping-pong sets)
__device__ __half d_ah0[B_DIM * M_DIM];
__device__ __half d_al0[B_DIM * M_DIM];
__device__ __half d_ah1[B_DIM * M_DIM];
__device__ __half d_al1[B_DIM * M_DIM];
__device__ float d_partial[4 * B_DIM * C_DIM];   // L3 split-K partials
__device__ float d_logits[B_DIM * C_DIM];
__device__ uint32_t d_subkeys[2 * K_ITERS];
__device__ uint32_t d_key_ready;   // reset by presplit kernel each replay

// ---------------------------------------------------------------------------
// PTX helpers (portable to compute_103)
// ---------------------------------------------------------------------------
__device__ __forceinline__ uint32_t h2_bits(__half2 h) {
    uint32_t u;
    memcpy(&u, &h, 4);
    return u;
}
__device__ __forceinline__ uint32_t ld_acquire_u32(const uint32_t* p) {
    uint32_t v;
    asm volatile("ld.acquire.gpu.global.u32 %0, [%1];" : "=r"(v) : "l"(p) : "memory");
    return v;
}
__device__ __forceinline__ void st_release_u32(uint32_t* p, uint32_t v) {
    asm volatile("st.release.gpu.global.u32 [%0], %1;" :: "l"(p), "r"(v) : "memory");
}
__device__ __forceinline__ float ex2_approx(float x) {
    float r;
    asm("ex2.approx.f32 %0, %1;" : "=f"(r) : "f"(x));
    return r;
}
__device__ __forceinline__ void ldsm_x4(uint32_t& r0, uint32_t& r1, uint32_t& r2,
                                        uint32_t& r3, uint32_t addr) {
    asm volatile("ldmatrix.sync.aligned.m8n8.x4.shared.b16 {%0,%1,%2,%3}, [%4];"
                 : "=r"(r0), "=r"(r1), "=r"(r2), "=r"(r3) : "r"(addr));
}
__device__ __forceinline__ void ldsm_x2(uint32_t& r0, uint32_t& r1, uint32_t addr) {
    asm volatile("ldmatrix.sync.aligned.m8n8.x2.shared.b16 {%0,%1}, [%2];"
                 : "=r"(r0), "=r"(r1) : "r"(addr));
}
__device__ __forceinline__ void mma_fp16(float* c, const uint32_t* a, const uint32_t* b) {
    asm volatile(
        "mma.sync.aligned.m16n8k16.row.col.f32.f16.f16.f32 "
        "{%0,%1,%2,%3}, {%4,%5,%6,%7}, {%8,%9}, {%0,%1,%2,%3};"
        : "+f"(c[0]), "+f"(c[1]), "+f"(c[2]), "+f"(c[3])
        : "r"(a[0]), "r"(a[1]), "r"(a[2]), "r"(a[3]), "r"(b[0]), "r"(b[1]));
}
__device__ __forceinline__ void cp_async16(uint32_t dst, const void* src) {
    asm volatile("cp.async.cg.shared.global [%0], [%1], 16;" :: "r"(dst), "l"(src));
}
__device__ __forceinline__ void cp_commit() {
    asm volatile("cp.async.commit_group;" ::: "memory");
}
template <int N>
__device__ __forceinline__ void cp_wait() {
    asm volatile("cp.async.wait_group %0;" :: "n"(N) : "memory");
}

// ---------------------------------------------------------------------------
// threefry2x32 (JAX-exact, partitionable semantics)
// ---------------------------------------------------------------------------
__device__ __forceinline__ void tf_round(uint32_t& x0, uint32_t& x1, int d) {
    x0 += x1;
    x1 = __funnelshift_l(x1, x1, d);
    x1 ^= x0;
}
__device__ __forceinline__ void threefry2x32(uint32_t k0, uint32_t k1, uint32_t k2,
                                             uint32_t x0, uint32_t x1,
                                             uint32_t& o0, uint32_t& o1) {
    x0 += k0; x1 += k1;
    tf_round(x0, x1, 13); tf_round(x0, x1, 15); tf_round(x0, x1, 26); tf_round(x0, x1, 6);
    x0 += k1; x1 += k2 + 1u;
    tf_round(x0, x1, 17); tf_round(x0, x1, 29); tf_round(x0, x1, 16); tf_round(x0, x1, 24);
    x0 += k2; x1 += k0 + 2u;
    tf_round(x0, x1, 13); tf_round(x0, x1, 15); tf_round(x0, x1, 26); tf_round(x0, x1, 6);
    x0 += k0; x1 += k1 + 3u;
    tf_round(x0, x1, 17); tf_round(x0, x1, 29); tf_round(x0, x1, 16); tf_round(x0, x1, 24);
    x0 += k1; x1 += k2 + 4u;
    tf_round(x0, x1, 13); tf_round(x0, x1, 15); tf_round(x0, x1, 26); tf_round(x0, x1, 6);
    x0 += k2; x1 += k0 + 5u;
    o0 = x0; o1 = x1;
}

// ---------------------------------------------------------------------------
// presplit: f fp32 -> fp16 hi/lo pair; also resets the key-chain flag
// ---------------------------------------------------------------------------
__global__ void presplit_kernel(const float* __restrict__ f,
                                __half* __restrict__ Ah, __half* __restrict__ Al, int n) {
    int i = blockIdx.x * blockDim.x + threadIdx.x;
    if (i == 0) d_key_ready = 0;
    if (i < n) {
        float v = f[i];
        __half h = __float2half_rn(v);
        Ah[i] = h;
        Al[i] = __float2half_rn(v - __half2float(h));
    }
}

// ---------------------------------------------------------------------------
// GEMM: Y[128, NOUT], block tile 128 x NTILE, BK=64, 2 smem stages.
// NTILE=64 for all layers (halves per-chip A L2-traffic vs NTILE=32; grid
// 128 = one wave). MODE 1: fused BN+ReLU + split fp16 out. MODE 2: raw
// fp32 partial (split-K slice = blockIdx.y).
// ---------------------------------------------------------------------------
#define PITCH 144
#define A_HALF_BYTES 18432            // 128 rows * 144
#define A_BYTES      36864            // hi + lo

template <int NTILE>
struct GemmCfg {
    static constexpr int W_HALF = NTILE * PITCH;
    static constexpr int STAGE = A_BYTES + 2 * W_HALF;
    static constexpr int SMEM = 2 * STAGE;
    static constexpr int WPT = NTILE / 16;          // W float4 loads / thread
    static constexpr int WARPS_N = (NTILE == 64) ? 4 : (NTILE == 32 ? 2 : 1);
    static constexpr int WARPS_M = 8 / WARPS_N;
    static constexpr int MT = 128 / (WARPS_M * 16);
};

__device__ __forceinline__ void issue_A(uint32_t sb, const __half* Ah_g,
                                        const __half* Al_g, int Kstr, int kc, int tid) {
#pragma unroll
    for (int p = 0; p < 8; p++) {
        int idx = tid + p * 256;            // 0..2047 16B chunks
        int hsel = idx >> 10;
        int rem = idx & 1023;
        int row = rem >> 3, seg = rem & 7;
        const __half* src = (hsel ? Al_g : Ah_g) + (size_t)row * Kstr + kc * 64 + seg * 8;
        uint32_t dst = sb + hsel * A_HALF_BYTES + row * PITCH + seg * 16;
        cp_async16(dst, src);
    }
}

__device__ __forceinline__ void sts_W_split(char* wh, char* wl, int row, int c4, float4 v) {
    __half2 h01 = __floats2half2_rn(v.x, v.y);
    __half2 h23 = __floats2half2_rn(v.z, v.w);
    float2 f01 = __half22float2(h01);
    float2 f23 = __half22float2(h23);
    __half2 l01 = __floats2half2_rn(v.x - f01.x, v.y - f01.y);
    __half2 l23 = __floats2half2_rn(v.z - f23.x, v.w - f23.y);
    uint32_t off = (uint32_t)(row * PITCH + c4 * 8);
    *(uint2*)(wh + off) = make_uint2(h2_bits(h01), h2_bits(h23));
    *(uint2*)(wl + off) = make_uint2(h2_bits(l01), h2_bits(l23));
}

template <int NTILE, int MODE>
__global__ void __launch_bounds__(256, 1) gemm_bn_kernel(
    const __half* __restrict__ Ah_g, const __half* __restrict__ Al_g,
    const float* __restrict__ W,
    const float* __restrict__ gamma, const float* __restrict__ beta,
    float* __restrict__ Yf, __half* __restrict__ Yh, __half* __restrict__ Yl,
    int K, int Kstr, int NOUT) {
    using C = GemmCfg<NTILE>;
    extern __shared__ char sm[];
    const uint32_t smb = (uint32_t)__cvta_generic_to_shared(sm);

    const int tid = threadIdx.x;
    const int wid = tid >> 5;
    const int lane = tid & 31;
    const int colBase = blockIdx.x * NTILE;
    const int koff = blockIdx.y * K;       // split-K slice offset (0 otherwise)
    Ah_g += koff;
    Al_g += koff;

    const int row0 = (wid / C::WARPS_N) * (C::MT * 16);
    const int col0 = (wid % C::WARPS_N) * 16;
    const int a_sub = lane >> 3;
    const int a_row = (a_sub & 1) * 8 + (lane & 7);
    const int a_kh = (a_sub >> 1) * 16;
    const int b_nrow = lane & 7;
    const int b_kh = ((lane >> 3) & 1) * 16;

    float acc[C::MT][2][4];
#pragma unroll
    for (int mt = 0; mt < C::MT; mt++)
#pragma unroll
        for (int nt = 0; nt < 2; nt++)
#pragma unroll
            for (int i = 0; i < 4; i++) acc[mt][nt][i] = 0.0f;

    const int nch = K >> 6;
    const float* Wb0 = W + (size_t)colBase * Kstr + koff;
    float4 wr[C::WPT];

    issue_A(smb, Ah_g, Al_g, Kstr, 0, tid);
    cp_commit();
#pragma unroll
    for (int p = 0; p < C::WPT; p++) {
        int idx = tid + p * 256;
        wr[p] = *(const float4*)(Wb0 + (size_t)(idx >> 4) * Kstr + (idx & 15) * 4);
    }

    for (int kc = 0; kc < nch; kc++) {
        const int s = kc & 1;
        const uint32_t sb = smb + s * C::STAGE;
        char* sb_p = sm + s * C::STAGE;

        if (kc + 1 < nch) issue_A(smb + (s ^ 1) * C::STAGE, Ah_g, Al_g, Kstr, kc + 1, tid);
        cp_commit();

        // convert+store W(kc) from regs
        char* whp = sb_p + A_BYTES;
        char* wlp = sb_p + A_BYTES + C::W_HALF;
#pragma unroll
        for (int p = 0; p < C::WPT; p++) {
            int idx = tid + p * 256;
            sts_W_split(whp, wlp, idx >> 4, idx & 15, wr[p]);
        }
        // prefetch W(kc+1)
        if (kc + 1 < nch) {
            const float* Wb = Wb0 + (kc + 1) * 64;
#pragma unroll
            for (int p = 0; p < C::WPT; p++) {
                int idx = tid + p * 256;
                wr[p] = *(const float4*)(Wb + (size_t)(idx >> 4) * Kstr + (idx & 15) * 4);
            }
        }
        cp_wait<1>();           // A(kc) resident (A(kc+1) may be in flight)
        __syncthreads();

        const uint32_t ah_b = sb;
        const uint32_t al_b = sb + A_HALF_BYTES;
        const uint32_t wh_b = sb + A_BYTES;
        const uint32_t wl_b = sb + A_BYTES + C::W_HALF;
#pragma unroll
        for (int ks = 0; ks < 4; ks++) {
            uint32_t ahf[C::MT][4], alf[C::MT][4];
#pragma unroll
            for (int mt = 0; mt < C::MT; mt++) {
                uint32_t boff = (uint32_t)((row0 + mt * 16 + a_row) * PITCH + ks * 32 + a_kh);
                ldsm_x4(ahf[mt][0], ahf[mt][1], ahf[mt][2], ahf[mt][3], ah_b + boff);
                ldsm_x4(alf[mt][0], alf[mt][1], alf[mt][2], alf[mt][3], al_b + boff);
            }
            uint32_t bhf[2][2], blf[2][2];
#pragma unroll
            for (int nt = 0; nt < 2; nt++) {
                uint32_t boff = (uint32_t)((col0 + nt * 8 + b_nrow) * PITCH + ks * 32 + b_kh);
                ldsm_x2(bhf[nt][0], bhf[nt][1], wh_b + boff);
                ldsm_x2(blf[nt][0], blf[nt][1], wl_b + boff);
            }
#pragma unroll
            for (int mt = 0; mt < C::MT; mt++)
#pragma unroll
                for (int nt = 0; nt < 2; nt++) {
                    mma_fp16(acc[mt][nt], ahf[mt], bhf[nt]);
                    mma_fp16(acc[mt][nt], ahf[mt], blf[nt]);
                    mma_fp16(acc[mt][nt], alf[mt], bhf[nt]);
                }
        }
        __syncthreads();
    }

    // -------- epilogue -----------------------------------------------------
    float* tile = (float*)sm;                       // 128 x (NTILE+1)
    const int TP = NTILE + 1;
    const int g = lane >> 2, tq = lane & 3;
#pragma unroll
    for (int mt = 0; mt < C::MT; mt++)
#pragma unroll
        for (int nt = 0; nt < 2; nt++) {
            int rr = row0 + mt * 16 + g;
            int cc = col0 + nt * 8 + tq * 2;
            tile[rr * TP + cc] = acc[mt][nt][0];
            tile[rr * TP + cc + 1] = acc[mt][nt][1];
            tile[(rr + 8) * TP + cc] = acc[mt][nt][2];
            tile[(rr + 8) * TP + cc + 1] = acc[mt][nt][3];
        }
    __syncthreads();

    if (MODE == 2) {
        // raw partial: Yf + slice offset
        float* P = Yf + (size_t)blockIdx.y * B_DIM * NOUT;
#pragma unroll
        for (int p = 0; p < NTILE / 2; p++) {
            int idx = tid + p * 256;
            int r = idx / NTILE, c = idx % NTILE;
            P[(size_t)r * NOUT + colBase + c] = tile[r * TP + c];
        }
        return;
    }

    float* stats = (float*)(sm + ((128 * TP * 4 + 127) & ~127));
    float* sm_mu = stats;
    float* sm_rs = stats + NTILE;
    float* sm_ga = stats + 2 * NTILE;
    float* sm_be = stats + 3 * NTILE;
    if (tid < NTILE) {
        float s = 0.0f, s2 = 0.0f;
#pragma unroll 8
        for (int r = 0; r < 128; r++) {
            float v = tile[r * TP + tid];
            s += v;
            s2 += v * v;
        }
        float mu = s * (1.0f / 128.0f);
        float var = s2 * (1.0f / 128.0f) - mu * mu;
        sm_mu[tid] = mu;
        sm_rs[tid] = rsqrtf(var + 1e-5f);
        sm_ga[tid] = gamma[colBase + tid];
        sm_be[tid] = beta[colBase + tid];
    }
    __syncthreads();
#pragma unroll
    for (int p = 0; p < NTILE / 2; p++) {
        int idx = tid + p * 256;
        int r = idx / NTILE, c = idx % NTILE;
        float v = tile[r * TP + c];
        float y = fmaxf((v - sm_mu[c]) * sm_rs[c] * sm_ga[c] + sm_be[c], 0.0f);
        size_t o = (size_t)r * NOUT + colBase + c;
        __half h = __float2half_rn(y);
        Yh[o] = h;
        Yl[o] = __float2half_rn(y - __half2float(h));
    }
}

// ---------------------------------------------------------------------------
// bn_reduce: sum 4 split-K partials, batch-stats over 128 rows, normalize
// ---------------------------------------------------------------------------
__global__ void __launch_bounds__(256) bn_reduce_kernel(
    const float* __restrict__ part, float* __restrict__ logits) {
    int c = blockIdx.x * 256 + threadIdx.x;     // 2048 columns
    float s = 0.0f, s2 = 0.0f;
#pragma unroll 4
    for (int r = 0; r < B_DIM; r++) {
        float v = part[r * C_DIM + c]
                + part[(B_DIM + r) * C_DIM + c]
                + part[(2 * B_DIM + r) * C_DIM + c]
                + part[(3 * B_DIM + r) * C_DIM + c];
        s += v;
        s2 += v * v;
    }
    float mu = s * (1.0f / 128.0f);
    float var = s2 * (1.0f / 128.0f) - mu * mu;
    float rs = rsqrtf(var + 1e-5f);
#pragma unroll 4
    for (int r = 0; r < B_DIM; r++) {
        float v = part[r * C_DIM + c]
                + part[(B_DIM + r) * C_DIM + c]
                + part[(2 * B_DIM + r) * C_DIM + c]
                + part[(3 * B_DIM + r) * C_DIM + c];
        logits[r * C_DIM + c] = (v - mu) * rs;
    }
}

// ---------------------------------------------------------------------------
// Softmax-numerator exponent, fully folded (TAU=0.5):
//   exp((mask+g)*2) = exp2( 2.8853902*mask + 1.0575375 - 2*log2(-log2 u) )
// ---------------------------------------------------------------------------
__device__ __forceinline__ float num_exp(uint32_t bits, float mask) {
    uint32_t mb = bits >> 9;
    float f = __uint_as_float(mb | 0x3f800000u) - 1.0f;   // exact in [0,1)
    float u = f + F32_TINY;
    float d = 1.0f - f;                                    // exact
    float Ls = -(d * (1.0f + d * (0.5f + d * (0.33333334f + d * 0.25f))));
    float t = (d < 0.00390625f) ? Ls * 1.4426950f : __log2f(u);   // log2(u) < 0
    float arg = fmaf(mask, 2.8853902f, 1.0575375f);
    arg = fmaf(__log2f(-t), -2.0f, arg);
    return ex2_approx(arg);
}

// ---------------------------------------------------------------------------
// scan: blocks 0..127 consume (128 threads x 16 cols); block 128 produces
// the sequential key chain. 4-warp barrier; combine via 1x LDS.128 + 3 FADD.
// Same per-SMSP issue floor as 256x8, but less barrier skew.
// ---------------------------------------------------------------------------
__global__ void __launch_bounds__(128, 1) gumbel_scan_kernel(
    const float* __restrict__ logits, float* __restrict__ z_out) {
    if (blockIdx.x == B_DIM) {
        if (threadIdx.x == 0) {
            uint32_t k0 = 0u, k1 = 42u;
            for (int t = 0; t < K_ITERS; t++) {
                uint32_t kx = k0 ^ k1 ^ 0x1BD11BDAu;
                uint32_t a0, a1, b0, b1;
                threefry2x32(k0, k1, kx, 0u, 0u, a0, a1);  // new key
                threefry2x32(k0, k1, kx, 0u, 1u, b0, b1);  // subkey
                d_subkeys[2 * t] = b0;
                d_subkeys[2 * t + 1] = b1;
                st_release_u32(&d_key_ready, (uint32_t)(t + 1));
                k0 = a0; k1 = a1;
            }
        }
        return;
    }

    const int r = blockIdx.x;
    const int tid = threadIdx.x;
    const int lane = tid & 31;
    const int wid = tid >> 5;                    // 4 warps
    const uint32_t ibase = (uint32_t)r * 2048u + (uint32_t)tid;

    __shared__ __align__(16) float redB[2][4];
    __shared__ uint32_t skey[64];

    float mask[16], z[16];
#pragma unroll
    for (int i = 0; i < 16; i++) {
        mask[i] = logits[r * C_DIM + tid + 128 * i];
        z[i] = 0.0f;
    }

    for (int t = 0; t < K_ITERS; t++) {
        if ((t & 31) == 0) {
            __syncthreads();   // retire prior skey reads
            if (tid == 0) {
                uint32_t need = (uint32_t)(t + 32);
                while (ld_acquire_u32(&d_key_ready) < need) {}
            }
            __syncthreads();
            if (tid < 64) skey[tid] = d_subkeys[2 * t + tid];
            __syncthreads();
        }
        const uint32_t k0 = skey[(t & 31) * 2];
        const uint32_t k1 = skey[(t & 31) * 2 + 1];
        const uint32_t k2 = k0 ^ k1 ^ 0x1BD11BDAu;

        float e[16];
        float sm = 0.0f;
#pragma unroll
        for (int i = 0; i < 16; i++) {
            uint32_t idx = ibase + 128u * (uint32_t)i;
            uint32_t o0, o1;
            threefry2x32(k0, k1, k2, 0u, idx, o0, o1);
            e[i] = num_exp(o0 ^ o1, mask[i]);
            sm += e[i];
        }
#pragma unroll
        for (int o = 16; o > 0; o >>= 1) sm += __shfl_xor_sync(0xffffffffu, sm, o);
        if (lane == 0) redB[t & 1][wid] = sm;
        __syncthreads();
        // combine: 4 partials via one 16B broadcast load + FADD tree
        float4 pa = *(const float4*)&redB[t & 1][0];
        sm = (pa.x + pa.y) + (pa.z + pa.w);

        float inv = __fdividef(1.0f, sm);
#pragma unroll
        for (int i = 0; i < 16; i++) {
            mask[i] = e[i] * inv;
            z[i] = fmaxf(z[i], mask[i]);
        }
    }

#pragma unroll
    for (int i = 0; i < 16; i++) z_out[r * C_DIM + tid + 128 * i] = z[i];
}

// ---------------------------------------------------------------------------
// Launch
// ---------------------------------------------------------------------------
extern "C" void kernel_launch(void* const* d_in, const int* in_sizes, int n_in,
                              void* d_out, int out_size) {
    const float* f   = (const float*)d_in[0];
    const float* w1  = (const float*)d_in[1];
    const float* g1  = (const float*)d_in[3];
    const float* be1 = (const float*)d_in[4];
    const float* w2  = (const float*)d_in[5];
    const float* g2  = (const float*)d_in[7];
    const float* be2 = (const float*)d_in[8];
    const float* w3  = (const float*)d_in[9];
    float* out = (float*)d_out;

    __half* ah0; cudaGetSymbolAddress((void**)&ah0, d_ah0);
    __half* al0; cudaGetSymbolAddress((void**)&al0, d_al0);
    __half* ah1; cudaGetSymbolAddress((void**)&ah1, d_ah1);
    __half* al1; cudaGetSymbolAddress((void**)&al1, d_al1);
    float* part;   cudaGetSymbolAddress((void**)&part, d_partial);
    float* logits; cudaGetSymbolAddress((void**)&logits, d_logits);

    constexpr int SMEM64 = GemmCfg<64>::SMEM;   // 110592
    cudaFuncSetAttribute(gemm_bn_kernel<64, 1>,
                         cudaFuncAttributeMaxDynamicSharedMemorySize, SMEM64);
    cudaFuncSetAttribute(gemm_bn_kernel<64, 2>,
                         cudaFuncAttributeMaxDynamicSharedMemorySize, SMEM64);

    // split f into fp16 hi/lo (set 0); also resets key flag
    presplit_kernel<<<(B_DIM * D_DIM + 255) / 256, 256>>>(f, ah0, al0, B_DIM * D_DIM);

    // L1: [128,2048] x [8192,2048]^T -> BN+ReLU -> split set1 (bias cancels)
    gemm_bn_kernel<64, 1><<<M_DIM / 64, 256, SMEM64>>>(
        ah0, al0, w1, g1, be1, nullptr, ah1, al1, D_DIM, D_DIM, M_DIM);
    // L2: [128,8192] x [8192,8192]^T -> BN+ReLU -> split set0
    gemm_bn_kernel<64, 1><<<M_DIM / 64, 256, SMEM64>>>(
        ah1, al1, w2, g2, be2, nullptr, ah0, al0, M_DIM, M_DIM, M_DIM);
    // L3 split-K: [128,8192] x [2048,8192]^T in 4 K-slices -> partials
    gemm_bn_kernel<64, 2><<<dim3(C_DIM / 64, 4), 256, SMEM64>>>(
        ah0, al0, w3, nullptr, nullptr, part, nullptr, nullptr,
        M_DIM / 4, M_DIM, C_DIM);
    // reduce partials + final BN (affine=False)
    bn_reduce_kernel<<<C_DIM / 256, 256>>>(part, logits);

    gumbel_scan_kernel<<<B_DIM + 1, 128>>>(logits, out);
}

// round 15
// speedup vs baseline: 1.0650x; 1.0650x over previous
#include <cuda_runtime.h>
#include <cuda_bf16.h>
#include <cuda_fp16.h>
#include <cstdint>
#include <cstring>

// ---------------------------------------------------------------------------
// B=128, D=2048, M=8192, C=2048, K_ITERS=1024, TAU=0.5
// ---------------------------------------------------------------------------
#define B_DIM 128
#define D_DIM 2048
#define M_DIM 8192
#define C_DIM 2048
#define K_ITERS 1024
#define F32_TINY 1.17549435e-38f

// fp16 split activation buffers (ping-pong sets)
__device__ __half d_ah0[B_DIM * M_DIM];
__device__ __half d_al0[B_DIM * M_DIM];
__device__ __half d_ah1[B_DIM * M_DIM];
__device__ __half d_al1[B_DIM * M_DIM];
__device__ float d_partial[4 * B_DIM * C_DIM];   // L3 split-K partials
__device__ float d_logits[B_DIM * C_DIM];
__device__ uint32_t d_subkeys[2 * K_ITERS];
__device__ uint32_t d_key_ready;   // reset by presplit kernel each replay

// ---------------------------------------------------------------------------
// PTX helpers (portable to compute_103)
// ---------------------------------------------------------------------------
__device__ __forceinline__ uint32_t h2_bits(__half2 h) {
    uint32_t u;
    memcpy(&u, &h, 4);
    return u;
}
__device__ __forceinline__ uint32_t ld_acquire_u32(const uint32_t* p) {
    uint32_t v;
    asm volatile("ld.acquire.gpu.global.u32 %0, [%1];" : "=r"(v) : "l"(p) : "memory");
    return v;
}
__device__ __forceinline__ void st_release_u32(uint32_t* p, uint32_t v) {
    asm volatile("st.release.gpu.global.u32 [%0], %1;" :: "l"(p), "r"(v) : "memory");
}
__device__ __forceinline__ float ex2_approx(float x) {
    float r;
    asm("ex2.approx.f32 %0, %1;" : "=f"(r) : "f"(x));
    return r;
}
__device__ __forceinline__ void ldsm_x4(uint32_t& r0, uint32_t& r1, uint32_t& r2,
                                        uint32_t& r3, uint32_t addr) {
    asm volatile("ldmatrix.sync.aligned.m8n8.x4.shared.b16 {%0,%1,%2,%3}, [%4];"
                 : "=r"(r0), "=r"(r1), "=r"(r2), "=r"(r3) : "r"(addr));
}
__device__ __forceinline__ void ldsm_x2(uint32_t& r0, uint32_t& r1, uint32_t addr) {
    asm volatile("ldmatrix.sync.aligned.m8n8.x2.shared.b16 {%0,%1}, [%2];"
                 : "=r"(r0), "=r"(r1) : "r"(addr));
}
__device__ __forceinline__ void mma_fp16(float* c, const uint32_t* a, const uint32_t* b) {
    asm volatile(
        "mma.sync.aligned.m16n8k16.row.col.f32.f16.f16.f32 "
        "{%0,%1,%2,%3}, {%4,%5,%6,%7}, {%8,%9}, {%0,%1,%2,%3};"
        : "+f"(c[0]), "+f"(c[1]), "+f"(c[2]), "+f"(c[3])
        : "r"(a[0]), "r"(a[1]), "r"(a[2]), "r"(a[3]), "r"(b[0]), "r"(b[1]));
}
__device__ __forceinline__ void cp_async16(uint32_t dst, const void* src) {
    asm volatile("cp.async.cg.shared.global [%0], [%1], 16;" :: "r"(dst), "l"(src));
}
__device__ __forceinline__ void cp_commit() {
    asm volatile("cp.async.commit_group;" ::: "memory");
}
template <int N>
__device__ __forceinline__ void cp_wait() {
    asm volatile("cp.async.wait_group %0;" :: "n"(N) : "memory");
}

// ---------------------------------------------------------------------------
// threefry2x32 (JAX-exact, partitionable semantics)
// ---------------------------------------------------------------------------
__device__ __forceinline__ void tf_round(uint32_t& x0, uint32_t& x1, int d) {
    x0 += x1;
    x1 = __funnelshift_l(x1, x1, d);
    x1 ^= x0;
}
__device__ __forceinline__ void threefry2x32(uint32_t k0, uint32_t k1, uint32_t k2,
                                             uint32_t x0, uint32_t x1,
                                             uint32_t& o0, uint32_t& o1) {
    x0 += k0; x1 += k1;
    tf_round(x0, x1, 13); tf_round(x0, x1, 15); tf_round(x0, x1, 26); tf_round(x0, x1, 6);
    x0 += k1; x1 += k2 + 1u;
    tf_round(x0, x1, 17); tf_round(x0, x1, 29); tf_round(x0, x1, 16); tf_round(x0, x1, 24);
    x0 += k2; x1 += k0 + 2u;
    tf_round(x0, x1, 13); tf_round(x0, x1, 15); tf_round(x0, x1, 26); tf_round(x0, x1, 6);
    x0 += k0; x1 += k1 + 3u;
    tf_round(x0, x1, 17); tf_round(x0, x1, 29); tf_round(x0, x1, 16); tf_round(x0, x1, 24);
    x0 += k1; x1 += k2 + 4u;
    tf_round(x0, x1, 13); tf_round(x0, x1, 15); tf_round(x0, x1, 26); tf_round(x0, x1, 6);
    x0 += k2; x1 += k0 + 5u;
    o0 = x0; o1 = x1;
}

// ---------------------------------------------------------------------------
// presplit: f fp32 -> fp16 hi/lo pair; also resets the key-chain flag
// ---------------------------------------------------------------------------
__global__ void presplit_kernel(const float* __restrict__ f,
                                __half* __restrict__ Ah, __half* __restrict__ Al, int n) {
    int i = blockIdx.x * blockDim.x + threadIdx.x;
    if (i == 0) d_key_ready = 0;
    if (i < n) {
        float v = f[i];
        __half h = __float2half_rn(v);
        Ah[i] = h;
        Al[i] = __float2half_rn(v - __half2float(h));
    }
}

// ---------------------------------------------------------------------------
// GEMM: Y[128, NOUT], block tile 128 x 64, BK=64, 2 smem stages.
// NTILE=64 all layers (halves per-chip A L2 traffic vs 32; grid 128 = 1 wave)
// MODE 1: fused BN+ReLU + split fp16 out. MODE 2: raw fp32 partial (split-K).
// ---------------------------------------------------------------------------
#define PITCH 144
#define A_HALF_BYTES 18432            // 128 rows * 144
#define A_BYTES      36864            // hi + lo

template <int NTILE>
struct GemmCfg {
    static constexpr int W_HALF = NTILE * PITCH;
    static constexpr int STAGE = A_BYTES + 2 * W_HALF;
    static constexpr int SMEM = 2 * STAGE;
    static constexpr int WPT = NTILE / 16;          // W float4 loads / thread
    static constexpr int WARPS_N = (NTILE == 64) ? 4 : (NTILE == 32 ? 2 : 1);
    static constexpr int WARPS_M = 8 / WARPS_N;
    static constexpr int MT = 128 / (WARPS_M * 16);
};

__device__ __forceinline__ void issue_A(uint32_t sb, const __half* Ah_g,
                                        const __half* Al_g, int Kstr, int kc, int tid) {
#pragma unroll
    for (int p = 0; p < 8; p++) {
        int idx = tid + p * 256;            // 0..2047 16B chunks
        int hsel = idx >> 10;
        int rem = idx & 1023;
        int row = rem >> 3, seg = rem & 7;
        const __half* src = (hsel ? Al_g : Ah_g) + (size_t)row * Kstr + kc * 64 + seg * 8;
        uint32_t dst = sb + hsel * A_HALF_BYTES + row * PITCH + seg * 16;
        cp_async16(dst, src);
    }
}

__device__ __forceinline__ void sts_W_split(char* wh, char* wl, int row, int c4, float4 v) {
    __half2 h01 = __floats2half2_rn(v.x, v.y);
    __half2 h23 = __floats2half2_rn(v.z, v.w);
    float2 f01 = __half22float2(h01);
    float2 f23 = __half22float2(h23);
    __half2 l01 = __floats2half2_rn(v.x - f01.x, v.y - f01.y);
    __half2 l23 = __floats2half2_rn(v.z - f23.x, v.w - f23.y);
    uint32_t off = (uint32_t)(row * PITCH + c4 * 8);
    *(uint2*)(wh + off) = make_uint2(h2_bits(h01), h2_bits(h23));
    *(uint2*)(wl + off) = make_uint2(h2_bits(l01), h2_bits(l23));
}

template <int NTILE, int MODE>
__global__ void __launch_bounds__(256, 1) gemm_bn_kernel(
    const __half* __restrict__ Ah_g, const __half* __restrict__ Al_g,
    const float* __restrict__ W,
    const float* __restrict__ gamma, const float* __restrict__ beta,
    float* __restrict__ Yf, __half* __restrict__ Yh, __half* __restrict__ Yl,
    int K, int Kstr, int NOUT) {
    using C = GemmCfg<NTILE>;
    extern __shared__ char sm[];
    const uint32_t smb = (uint32_t)__cvta_generic_to_shared(sm);

    const int tid = threadIdx.x;
    const int wid = tid >> 5;
    const int lane = tid & 31;
    const int colBase = blockIdx.x * NTILE;
    const int koff = blockIdx.y * K;       // split-K slice offset (0 otherwise)
    Ah_g += koff;
    Al_g += koff;

    const int row0 = (wid / C::WARPS_N) * (C::MT * 16);
    const int col0 = (wid % C::WARPS_N) * 16;
    const int a_sub = lane >> 3;
    const int a_row = (a_sub & 1) * 8 + (lane & 7);
    const int a_kh = (a_sub >> 1) * 16;
    const int b_nrow = lane & 7;
    const int b_kh = ((lane >> 3) & 1) * 16;

    float acc[C::MT][2][4];
#pragma unroll
    for (int mt = 0; mt < C::MT; mt++)
#pragma unroll
        for (int nt = 0; nt < 2; nt++)
#pragma unroll
            for (int i = 0; i < 4; i++) acc[mt][nt][i] = 0.0f;

    const int nch = K >> 6;
    const float* Wb0 = W + (size_t)colBase * Kstr + koff;
    float4 wr[C::WPT];

    issue_A(smb, Ah_g, Al_g, Kstr, 0, tid);
    cp_commit();
#pragma unroll
    for (int p = 0; p < C::WPT; p++) {
        int idx = tid + p * 256;
        wr[p] = *(const float4*)(Wb0 + (size_t)(idx >> 4) * Kstr + (idx & 15) * 4);
    }

    for (int kc = 0; kc < nch; kc++) {
        const int s = kc & 1;
        const uint32_t sb = smb + s * C::STAGE;
        char* sb_p = sm + s * C::STAGE;

        if (kc + 1 < nch) issue_A(smb + (s ^ 1) * C::STAGE, Ah_g, Al_g, Kstr, kc + 1, tid);
        cp_commit();

        // convert+store W(kc) from regs
        char* whp = sb_p + A_BYTES;
        char* wlp = sb_p + A_BYTES + C::W_HALF;
#pragma unroll
        for (int p = 0; p < C::WPT; p++) {
            int idx = tid + p * 256;
            sts_W_split(whp, wlp, idx >> 4, idx & 15, wr[p]);
        }
        // prefetch W(kc+1)
        if (kc + 1 < nch) {
            const float* Wb = Wb0 + (kc + 1) * 64;
#pragma unroll
            for (int p = 0; p < C::WPT; p++) {
                int idx = tid + p * 256;
                wr[p] = *(const float4*)(Wb + (size_t)(idx >> 4) * Kstr + (idx & 15) * 4);
            }
        }
        cp_wait<1>();           // A(kc) resident (A(kc+1) may be in flight)
        __syncthreads();

        const uint32_t ah_b = sb;
        const uint32_t al_b = sb + A_HALF_BYTES;
        const uint32_t wh_b = sb + A_BYTES;
        const uint32_t wl_b = sb + A_BYTES + C::W_HALF;
#pragma unroll
        for (int ks = 0; ks < 4; ks++) {
            uint32_t ahf[C::MT][4], alf[C::MT][4];
#pragma unroll
            for (int mt = 0; mt < C::MT; mt++) {
                uint32_t boff = (uint32_t)((row0 + mt * 16 + a_row) * PITCH + ks * 32 + a_kh);
                ldsm_x4(ahf[mt][0], ahf[mt][1], ahf[mt][2], ahf[mt][3], ah_b + boff);
                ldsm_x4(alf[mt][0], alf[mt][1], alf[mt][2], alf[mt][3], al_b + boff);
            }
            uint32_t bhf[2][2], blf[2][2];
#pragma unroll
            for (int nt = 0; nt < 2; nt++) {
                uint32_t boff = (uint32_t)((col0 + nt * 8 + b_nrow) * PITCH + ks * 32 + b_kh);
                ldsm_x2(bhf[nt][0], bhf[nt][1], wh_b + boff);
                ldsm_x2(blf[nt][0], blf[nt][1], wl_b + boff);
            }
#pragma unroll
            for (int mt = 0; mt < C::MT; mt++)
#pragma unroll
                for (int nt = 0; nt < 2; nt++) {
                    mma_fp16(acc[mt][nt], ahf[mt], bhf[nt]);
                    mma_fp16(acc[mt][nt], ahf[mt], blf[nt]);
                    mma_fp16(acc[mt][nt], alf[mt], bhf[nt]);
                }
        }
        __syncthreads();
    }

    // -------- epilogue -----------------------------------------------------
    float* tile = (float*)sm;                       // 128 x (NTILE+1)
    const int TP = NTILE + 1;
    const int g = lane >> 2, tq = lane & 3;
#pragma unroll
    for (int mt = 0; mt < C::MT; mt++)
#pragma unroll
        for (int nt = 0; nt < 2; nt++) {
            int rr = row0 + mt * 16 + g;
            int cc = col0 + nt * 8 + tq * 2;
            tile[rr * TP + cc] = acc[mt][nt][0];
            tile[rr * TP + cc + 1] = acc[mt][nt][1];
            tile[(rr + 8) * TP + cc] = acc[mt][nt][2];
            tile[(rr + 8) * TP + cc + 1] = acc[mt][nt][3];
        }
    __syncthreads();

    if (MODE == 2) {
        // raw partial: Yf + slice offset
        float* P = Yf + (size_t)blockIdx.y * B_DIM * NOUT;
#pragma unroll
        for (int p = 0; p < NTILE / 2; p++) {
            int idx = tid + p * 256;
            int r = idx / NTILE, c = idx % NTILE;
            P[(size_t)r * NOUT + colBase + c] = tile[r * TP + c];
        }
        return;
    }

    float* stats = (float*)(sm + ((128 * TP * 4 + 127) & ~127));
    float* sm_mu = stats;
    float* sm_rs = stats + NTILE;
    float* sm_ga = stats + 2 * NTILE;
    float* sm_be = stats + 3 * NTILE;
    if (tid < NTILE) {
        float s = 0.0f, s2 = 0.0f;
#pragma unroll 8
        for (int r = 0; r < 128; r++) {
            float v = tile[r * TP + tid];
            s += v;
            s2 += v * v;
        }
        float mu = s * (1.0f / 128.0f);
        float var = s2 * (1.0f / 128.0f) - mu * mu;
        sm_mu[tid] = mu;
        sm_rs[tid] = rsqrtf(var + 1e-5f);
        sm_ga[tid] = gamma[colBase + tid];
        sm_be[tid] = beta[colBase + tid];
    }
    __syncthreads();
#pragma unroll
    for (int p = 0; p < NTILE / 2; p++) {
        int idx = tid + p * 256;
        int r = idx / NTILE, c = idx % NTILE;
        float v = tile[r * TP + c];
        float y = fmaxf((v - sm_mu[c]) * sm_rs[c] * sm_ga[c] + sm_be[c], 0.0f);
        size_t o = (size_t)r * NOUT + colBase + c;
        __half h = __float2half_rn(y);
        Yh[o] = h;
        Yl[o] = __float2half_rn(y - __half2float(h));
    }
}

// ---------------------------------------------------------------------------
// bn_reduce: sum 4 split-K partials, batch-stats over 128 rows, normalize
// ---------------------------------------------------------------------------
__global__ void __launch_bounds__(256) bn_reduce_kernel(
    const float* __restrict__ part, float* __restrict__ logits) {
    int c = blockIdx.x * 256 + threadIdx.x;     // 2048 columns
    float s = 0.0f, s2 = 0.0f;
#pragma unroll 4
    for (int r = 0; r < B_DIM; r++) {
        float v = part[r * C_DIM + c]
                + part[(B_DIM + r) * C_DIM + c]
                + part[(2 * B_DIM + r) * C_DIM + c]
                + part[(3 * B_DIM + r) * C_DIM + c];
        s += v;
        s2 += v * v;
    }
    float mu = s * (1.0f / 128.0f);
    float var = s2 * (1.0f / 128.0f) - mu * mu;
    float rs = rsqrtf(var + 1e-5f);
#pragma unroll 4
    for (int r = 0; r < B_DIM; r++) {
        float v = part[r * C_DIM + c]
                + part[(B_DIM + r) * C_DIM + c]
                + part[(2 * B_DIM + r) * C_DIM + c]
                + part[(3 * B_DIM + r) * C_DIM + c];
        logits[r * C_DIM + c] = (v - mu) * rs;
    }
}

// ---------------------------------------------------------------------------
// Softmax-numerator exponent, fully folded (TAU=0.5):
//   exp((mask+g)*2) = exp2( 2.8853902*mask + 1.0575375 - 2*log2(-log2 u) )
// ---------------------------------------------------------------------------
__device__ __forceinline__ float num_exp(uint32_t bits, float mask) {
    uint32_t mb = bits >> 9;
    float f = __uint_as_float(mb | 0x3f800000u) - 1.0f;   // exact in [0,1)
    float u = f + F32_TINY;
    float d = 1.0f - f;                                    // exact
    float Ls = -(d * (1.0f + d * (0.5f + d * (0.33333334f + d * 0.25f))));
    float t = (d < 0.00390625f) ? Ls * 1.4426950f : __log2f(u);   // log2(u) < 0
    float arg = fmaf(mask, 2.8853902f, 1.0575375f);
    arg = fmaf(__log2f(-t), -2.0f, arg);
    return ex2_approx(arg);
}

// ---------------------------------------------------------------------------
// scan (R13-proven shape): blocks 0..127 consume (256 threads x 8 cols);
// block 128 produces the sequential key chain. 8-warp barrier; combine via
// 2x LDS.128 + FADD tree. No max-subtraction (exp args bounded).
// ---------------------------------------------------------------------------
__global__ void __launch_bounds__(256, 1) gumbel_scan_kernel(
    const float* __restrict__ logits, float* __restrict__ z_out) {
    if (blockIdx.x == B_DIM) {
        if (threadIdx.x == 0) {
            uint32_t k0 = 0u, k1 = 42u;
            for (int t = 0; t < K_ITERS; t++) {
                uint32_t kx = k0 ^ k1 ^ 0x1BD11BDAu;
                uint32_t a0, a1, b0, b1;
                threefry2x32(k0, k1, kx, 0u, 0u, a0, a1);  // new key
                threefry2x32(k0, k1, kx, 0u, 1u, b0, b1);  // subkey
                d_subkeys[2 * t] = b0;
                d_subkeys[2 * t + 1] = b1;
                st_release_u32(&d_key_ready, (uint32_t)(t + 1));
                k0 = a0; k1 = a1;
            }
        }
        return;
    }

    const int r = blockIdx.x;
    const int tid = threadIdx.x;
    const int lane = tid & 31;
    const int wid = tid >> 5;                    // 8 warps
    const uint32_t ibase = (uint32_t)r * 2048u + (uint32_t)tid;

    __shared__ __align__(16) float redB[2][8];
    __shared__ uint32_t skey[64];

    float mask[8], z[8];
#pragma unroll
    for (int i = 0; i < 8; i++) {
        mask[i] = logits[r * C_DIM + tid + 256 * i];
        z[i] = 0.0f;
    }

    for (int t = 0; t < K_ITERS; t++) {
        if ((t & 31) == 0) {
            __syncthreads();   // retire prior skey reads
            if (tid == 0) {
                uint32_t need = (uint32_t)(t + 32);
                while (ld_acquire_u32(&d_key_ready) < need) {}
            }
            __syncthreads();
            if (tid < 64) skey[tid] = d_subkeys[2 * t + tid];
            __syncthreads();
        }
        const uint32_t k0 = skey[(t & 31) * 2];
        const uint32_t k1 = skey[(t & 31) * 2 + 1];
        const uint32_t k2 = k0 ^ k1 ^ 0x1BD11BDAu;

        float e[8];
        float sm = 0.0f;
#pragma unroll
        for (int i = 0; i < 8; i++) {
            uint32_t idx = ibase + 256u * (uint32_t)i;
            uint32_t o0, o1;
            threefry2x32(k0, k1, k2, 0u, idx, o0, o1);
            e[i] = num_exp(o0 ^ o1, mask[i]);
            sm += e[i];
        }
#pragma unroll
        for (int o = 16; o > 0; o >>= 1) sm += __shfl_xor_sync(0xffffffffu, sm, o);
        if (lane == 0) redB[t & 1][wid] = sm;
        __syncthreads();
        // combine: 8 partials via two 16B broadcast loads + FADD tree
        float4 pa = *(const float4*)&redB[t & 1][0];
        float4 pb = *(const float4*)&redB[t & 1][4];
        sm = ((pa.x + pa.y) + (pa.z + pa.w)) + ((pb.x + pb.y) + (pb.z + pb.w));

        float inv = __fdividef(1.0f, sm);
#pragma unroll
        for (int i = 0; i < 8; i++) {
            mask[i] = e[i] * inv;
            z[i] = fmaxf(z[i], mask[i]);
        }
    }

#pragma unroll
    for (int i = 0; i < 8; i++) z_out[r * C_DIM + tid + 256 * i] = z[i];
}

// ---------------------------------------------------------------------------
// Launch
// ---------------------------------------------------------------------------
extern "C" void kernel_launch(void* const* d_in, const int* in_sizes, int n_in,
                              void* d_out, int out_size) {
    const float* f   = (const float*)d_in[0];
    const float* w1  = (const float*)d_in[1];
    const float* g1  = (const float*)d_in[3];
    const float* be1 = (const float*)d_in[4];
    const float* w2  = (const float*)d_in[5];
    const float* g2  = (const float*)d_in[7];
    const float* be2 = (const float*)d_in[8];
    const float* w3  = (const float*)d_in[9];
    float* out = (float*)d_out;

    __half* ah0; cudaGetSymbolAddress((void**)&ah0, d_ah0);
    __half* al0; cudaGetSymbolAddress((void**)&al0, d_al0);
    __half* ah1; cudaGetSymbolAddress((void**)&ah1, d_ah1);
    __half* al1; cudaGetSymbolAddress((void**)&al1, d_al1);
    float* part;   cudaGetSymbolAddress((void**)&part, d_partial);
    float* logits; cudaGetSymbolAddress((void**)&logits, d_logits);

    constexpr int SMEM64 = GemmCfg<64>::SMEM;   // 110592
    cudaFuncSetAttribute(gemm_bn_kernel<64, 1>,
                         cudaFuncAttributeMaxDynamicSharedMemorySize, SMEM64);
    cudaFuncSetAttribute(gemm_bn_kernel<64, 2>,
                         cudaFuncAttributeMaxDynamicSharedMemorySize, SMEM64);

    // split f into fp16 hi/lo (set 0); also resets key flag
    presplit_kernel<<<(B_DIM * D_DIM + 255) / 256, 256>>>(f, ah0, al0, B_DIM * D_DIM);

    // L1: [128,2048] x [8192,2048]^T -> BN+ReLU -> split set1 (bias cancels)
    gemm_bn_kernel<64, 1><<<M_DIM / 64, 256, SMEM64>>>(
        ah0, al0, w1, g1, be1, nullptr, ah1, al1, D_DIM, D_DIM, M_DIM);
    // L2: [128,8192] x [8192,8192]^T -> BN+ReLU -> split set0
    gemm_bn_kernel<64, 1><<<M_DIM / 64, 256, SMEM64>>>(
        ah1, al1, w2, g2, be2, nullptr, ah0, al0, M_DIM, M_DIM, M_DIM);
    // L3 split-K: [128,8192] x [2048,8192]^T in 4 K-slices -> partials
    gemm_bn_kernel<64, 2><<<dim3(C_DIM / 64, 4), 256, SMEM64>>>(
        ah0, al0, w3, nullptr, nullptr, part, nullptr, nullptr,
        M_DIM / 4, M_DIM, C_DIM);
    // reduce partials + final BN (affine=False)
    bn_reduce_kernel<<<C_DIM / 256, 256>>>(part, logits);

    gumbel_scan_kernel<<<B_DIM + 1, 256>>>(logits, out);
}